// round 1
// baseline (speedup 1.0000x reference)
#include <cuda_runtime.h>
#include <math.h>

#define D_MODEL 1024
#define NHEADS  16
#define DEPTH   64
#define BATCH   2
#define SEQ     2048
#define MTOT    (BATCH*SEQ)   // 4096

// ---------------- scratch (device globals; no allocations allowed) ----------
__device__ float g_q[BATCH*NHEADS*SEQ*DEPTH];   // 16 MB, [B,H,S,64]
__device__ float g_k[BATCH*NHEADS*SEQ*DEPTH];
__device__ float g_v[BATCH*NHEADS*SEQ*DEPTH];
__device__ float g_ctx[BATCH*SEQ*D_MODEL];      // 16 MB, [B,S,1024]

// ---------------- projection GEMM: out = A[M,K] @ W[N,K]^T + bias ----------
constexpr int BM = 128, BN = 128, BK = 8, TM = 8, TN = 8;

template<int SPLIT>
__global__ __launch_bounds__(256)
void proj_gemm(const float* __restrict__ A, const float* __restrict__ W,
               const float* __restrict__ bias, float* __restrict__ out) {
    __shared__ float As[BK][BM];
    __shared__ float Bs[BK][BN];
    const int bm = blockIdx.y * BM;
    const int bn = blockIdx.x * BN;
    const int tid = threadIdx.x;
    const int lr = tid >> 1;            // 0..127 row within tile
    const int lc = (tid & 1) * 4;       // 0 or 4 (k offset)
    const int ty = tid >> 4, tx = tid & 15;

    float acc[TM][TN] = {};

    for (int k0 = 0; k0 < D_MODEL; k0 += BK) {
        float4 a4 = *(const float4*)(A + (size_t)(bm + lr) * D_MODEL + k0 + lc);
        float4 b4 = *(const float4*)(W + (size_t)(bn + lr) * D_MODEL + k0 + lc);
        As[lc+0][lr] = a4.x; As[lc+1][lr] = a4.y; As[lc+2][lr] = a4.z; As[lc+3][lr] = a4.w;
        Bs[lc+0][lr] = b4.x; Bs[lc+1][lr] = b4.y; Bs[lc+2][lr] = b4.z; Bs[lc+3][lr] = b4.w;
        __syncthreads();
        #pragma unroll
        for (int kk = 0; kk < BK; kk++) {
            float ra[TM], rb[TN];
            *(float4*)&ra[0] = *(const float4*)&As[kk][ty*TM];
            *(float4*)&ra[4] = *(const float4*)&As[kk][ty*TM + 4];
            *(float4*)&rb[0] = *(const float4*)&Bs[kk][tx*TN];
            *(float4*)&rb[4] = *(const float4*)&Bs[kk][tx*TN + 4];
            #pragma unroll
            for (int i = 0; i < TM; i++)
                #pragma unroll
                for (int j = 0; j < TN; j++)
                    acc[i][j] += ra[i] * rb[j];
        }
        __syncthreads();
    }

    #pragma unroll
    for (int i = 0; i < TM; i++) {
        const int m = bm + ty*TM + i;
        #pragma unroll
        for (int j = 0; j < TN; j++) {
            const int n = bn + tx*TN + j;
            float v = acc[i][j] + bias[n];
            if (SPLIT) {
                // destination: [B, H, S, DEPTH]
                const int b = m >> 11, s = m & 2047;
                const int h = n >> 6,  d = n & 63;
                out[(((size_t)(b*NHEADS + h) * SEQ) + s) * DEPTH + d] = v;
            } else {
                out[(size_t)m * D_MODEL + n] = v;
            }
        }
    }
}

// ---------------- flash attention: 64x64 tiles, depth 64 --------------------
constexpr int FB   = 64;   // q-tile rows == k-tile rows
constexpr int FSTR = 68;   // padded smem row stride (floats), 16B aligned

__global__ __launch_bounds__(256)
void flash_attn(const int* __restrict__ mask) {
    extern __shared__ float sm[];
    float* Qs  = sm;                    // [64][68]
    float* Ks  = Qs + FB*FSTR;
    float* Vs  = Ks + FB*FSTR;
    float* Ps  = Vs + FB*FSTR;
    float* pen = Ps + FB*FSTR;          // [64]

    const int qt  = blockIdx.x;         // q tile (32)
    const int h   = blockIdx.y;         // head  (16)
    const int b   = blockIdx.z;         // batch (2)
    const int tid = threadIdx.x;
    const int ty = tid >> 4, tx = tid & 15;
    const int r0 = ty * 4, c0 = tx * 4;

    const float* qbase = g_q + ((size_t)(b*NHEADS + h) * SEQ + qt*FB) * DEPTH;
    const float* kbase = g_k + (size_t)(b*NHEADS + h) * SEQ * DEPTH;
    const float* vbase = g_v + (size_t)(b*NHEADS + h) * SEQ * DEPTH;

    // load Q tile, pre-scaled by 1/sqrt(64)
    for (int i = tid; i < FB * (DEPTH/4); i += 256) {
        const int r = i >> 4, c4 = (i & 15) * 4;
        float4 v = *(const float4*)(qbase + r*DEPTH + c4);
        Qs[r*FSTR + c4 + 0] = v.x * 0.125f;
        Qs[r*FSTR + c4 + 1] = v.y * 0.125f;
        Qs[r*FSTR + c4 + 2] = v.z * 0.125f;
        Qs[r*FSTR + c4 + 3] = v.w * 0.125f;
    }

    float m_i[4] = {-1e30f, -1e30f, -1e30f, -1e30f};
    float l_i[4] = {0.f, 0.f, 0.f, 0.f};
    float acc[4][4] = {};

    for (int kt = 0; kt < SEQ/FB; kt++) {
        __syncthreads();   // previous iter's P@V done; also covers initial Q load
        for (int i = tid; i < FB * (DEPTH/4); i += 256) {
            const int r = i >> 4, c4 = (i & 15) * 4;
            float4 kv = *(const float4*)(kbase + (size_t)(kt*FB + r)*DEPTH + c4);
            float4 vv = *(const float4*)(vbase + (size_t)(kt*FB + r)*DEPTH + c4);
            Ks[r*FSTR + c4 + 0] = kv.x; Ks[r*FSTR + c4 + 1] = kv.y;
            Ks[r*FSTR + c4 + 2] = kv.z; Ks[r*FSTR + c4 + 3] = kv.w;
            Vs[r*FSTR + c4 + 0] = vv.x; Vs[r*FSTR + c4 + 1] = vv.y;
            Vs[r*FSTR + c4 + 2] = vv.z; Vs[r*FSTR + c4 + 3] = vv.w;
        }
        if (tid < FB)
            pen[tid] = -1e9f * (float)mask[b*SEQ + kt*FB + tid];
        __syncthreads();

        // S = Q @ K^T  (thread: 4 q-rows x 4 k-cols)
        float s[4][4] = {};
        #pragma unroll
        for (int kk = 0; kk < DEPTH; kk += 4) {
            float4 q4[4], k4[4];
            #pragma unroll
            for (int i = 0; i < 4; i++) q4[i] = *(const float4*)&Qs[(r0+i)*FSTR + kk];
            #pragma unroll
            for (int j = 0; j < 4; j++) k4[j] = *(const float4*)&Ks[(c0+j)*FSTR + kk];
            #pragma unroll
            for (int i = 0; i < 4; i++)
                #pragma unroll
                for (int j = 0; j < 4; j++)
                    s[i][j] += q4[i].x*k4[j].x + q4[i].y*k4[j].y
                             + q4[i].z*k4[j].z + q4[i].w*k4[j].w;
        }

        // mask + online softmax (row reduction across the 16 tx lanes)
        #pragma unroll
        for (int i = 0; i < 4; i++) {
            #pragma unroll
            for (int j = 0; j < 4; j++) s[i][j] += pen[c0 + j];
            float mx = fmaxf(fmaxf(s[i][0], s[i][1]), fmaxf(s[i][2], s[i][3]));
            #pragma unroll
            for (int off = 1; off < 16; off <<= 1)
                mx = fmaxf(mx, __shfl_xor_sync(0xffffffffu, mx, off));
            const float mnew = fmaxf(m_i[i], mx);
            const float corr = __expf(m_i[i] - mnew);
            float rsum = 0.f;
            #pragma unroll
            for (int j = 0; j < 4; j++) { s[i][j] = __expf(s[i][j] - mnew); rsum += s[i][j]; }
            #pragma unroll
            for (int off = 1; off < 16; off <<= 1)
                rsum += __shfl_xor_sync(0xffffffffu, rsum, off);
            l_i[i] = l_i[i] * corr + rsum;
            m_i[i] = mnew;
            #pragma unroll
            for (int j = 0; j < 4; j++) acc[i][j] *= corr;
            #pragma unroll
            for (int j = 0; j < 4; j++) Ps[(r0+i)*FSTR + c0 + j] = s[i][j];
        }
        __syncthreads();

        // acc += P @ V  (thread: 4 q-rows x 4 depth-cols at d0 = c0)
        #pragma unroll
        for (int kk = 0; kk < FB; kk += 4) {
            float4 p4[4], v4[4];
            #pragma unroll
            for (int i = 0; i < 4; i++) p4[i] = *(const float4*)&Ps[(r0+i)*FSTR + kk];
            #pragma unroll
            for (int u = 0; u < 4; u++) v4[u] = *(const float4*)&Vs[(kk+u)*FSTR + c0];
            #pragma unroll
            for (int i = 0; i < 4; i++) {
                acc[i][0] += p4[i].x*v4[0].x + p4[i].y*v4[1].x + p4[i].z*v4[2].x + p4[i].w*v4[3].x;
                acc[i][1] += p4[i].x*v4[0].y + p4[i].y*v4[1].y + p4[i].z*v4[2].y + p4[i].w*v4[3].y;
                acc[i][2] += p4[i].x*v4[0].z + p4[i].y*v4[1].z + p4[i].z*v4[2].z + p4[i].w*v4[3].z;
                acc[i][3] += p4[i].x*v4[0].w + p4[i].y*v4[1].w + p4[i].z*v4[2].w + p4[i].w*v4[3].w;
            }
        }
    }

    // epilogue: merged-head context [B,S,1024]
    #pragma unroll
    for (int i = 0; i < 4; i++) {
        const float inv = 1.0f / l_i[i];
        const int row = qt*FB + r0 + i;
        float* o = g_ctx + ((size_t)b*SEQ + row) * D_MODEL + h*DEPTH + c0;
        #pragma unroll
        for (int j = 0; j < 4; j++) o[j] = acc[i][j] * inv;
    }
}

// ---------------------------------------------------------------------------
extern "C" void kernel_launch(void* const* d_in, const int* in_sizes, int n_in,
                              void* d_out, int out_size) {
    const float* query = (const float*)d_in[0];
    const float* key   = (const float*)d_in[1];
    const float* value = (const float*)d_in[2];
    const int*   mask  = (const int*)  d_in[3];
    const float* Wq = (const float*)d_in[4];
    const float* bq = (const float*)d_in[5];
    const float* Wk = (const float*)d_in[6];
    const float* bk = (const float*)d_in[7];
    const float* Wv = (const float*)d_in[8];
    const float* bv = (const float*)d_in[9];
    const float* Wo = (const float*)d_in[10];
    const float* bo = (const float*)d_in[11];
    float* out = (float*)d_out;

    void *pq, *pk, *pv, *pctx;
    cudaGetSymbolAddress(&pq,   g_q);
    cudaGetSymbolAddress(&pk,   g_k);
    cudaGetSymbolAddress(&pv,   g_v);
    cudaGetSymbolAddress(&pctx, g_ctx);

    const dim3 gg(D_MODEL / BN, MTOT / BM);   // (8, 32)

    proj_gemm<1><<<gg, 256>>>(query, Wq, bq, (float*)pq);
    proj_gemm<1><<<gg, 256>>>(key,   Wk, bk, (float*)pk);
    proj_gemm<1><<<gg, 256>>>(value, Wv, bv, (float*)pv);

    const int smem_bytes = (4 * FB * FSTR + FB) * (int)sizeof(float);  // ~69.9 KB
    cudaFuncSetAttribute(flash_attn, cudaFuncAttributeMaxDynamicSharedMemorySize,
                         smem_bytes);
    flash_attn<<<dim3(SEQ/FB, NHEADS, BATCH), 256, smem_bytes>>>(mask);

    proj_gemm<0><<<gg, 256>>>((const float*)pctx, Wo, bo, out);
}

// round 3
// speedup vs baseline: 1.3448x; 1.3448x over previous
#include <cuda_runtime.h>
#include <cstdint>
#include <math.h>

#define D_MODEL 1024
#define NHEADS  16
#define DEPTH   64
#define BATCH   2
#define SEQ     2048
#define MTOT    (BATCH*SEQ)   // 4096

// ---------------- scratch (device globals; no allocations allowed) ----------
__device__ float g_q[BATCH*NHEADS*SEQ*DEPTH];   // 16 MB, [B,H,S,64]
__device__ float g_k[BATCH*NHEADS*SEQ*DEPTH];
__device__ float g_v[BATCH*NHEADS*SEQ*DEPTH];
__device__ float g_ctx[BATCH*SEQ*D_MODEL];      // 16 MB, [B,S,1024]

// ---------------- mma.sync tf32 helpers (base-target, lowers to HMMA) ------
__device__ __forceinline__ uint32_t f2tf32(float x) {
    uint32_t r;
    asm("cvt.rna.tf32.f32 %0, %1;" : "=r"(r) : "f"(x));
    return r;
}
__device__ __forceinline__ void mma_tf32_16x8x8(float* d, const uint32_t* a,
                                                const uint32_t* b) {
    asm volatile(
        "mma.sync.aligned.m16n8k8.row.col.f32.tf32.tf32.f32 "
        "{%0,%1,%2,%3}, {%4,%5,%6,%7}, {%8,%9}, {%0,%1,%2,%3};"
        : "+f"(d[0]), "+f"(d[1]), "+f"(d[2]), "+f"(d[3])
        : "r"(a[0]), "r"(a[1]), "r"(a[2]), "r"(a[3]), "r"(b[0]), "r"(b[1]));
}

// ============ tf32 tensor-core projection: out = A[M,K] @ W[N,K]^T + bias ===
// CTA tile 128x128, 8 warps in 2x4 layout, warp tile 64x32 (4x4 m16n8k8),
// K staged 32 floats at a time in padded shared memory.
constexpr int PBM = 128, PBN = 128, PBK = 32, PLD = PBK + 4;   // PLD=36

template<int SPLIT>
__global__ __launch_bounds__(256)
void proj_mma(const float* __restrict__ A, const float* __restrict__ W,
              const float* __restrict__ bias, float* __restrict__ out) {
    __shared__ uint32_t As[PBM * PLD];
    __shared__ uint32_t Bs[PBN * PLD];

    const int tid  = threadIdx.x;
    const int wid  = tid >> 5;
    const int lane = tid & 31;
    const int g    = lane >> 2;          // group row 0..7
    const int tg   = lane & 3;           // 0..3
    const int wm   = wid >> 2;           // 0..1  (64 rows each)
    const int wn   = wid & 3;            // 0..3  (32 cols each)
    const int bm   = blockIdx.y * PBM;
    const int bn   = blockIdx.x * PBN;

    float acc[4][4][4] = {};             // [mi][ni][frag]

    for (int k0 = 0; k0 < D_MODEL; k0 += PBK) {
        // stage: 128x32 floats of A and W, tf32-converted (RNE)
        #pragma unroll
        for (int i = 0; i < 4; i++) {
            const int idx = tid + i * 256;        // 0..1023 float4 slots
            const int r = idx >> 3;               // 0..127
            const int c = (idx & 7) * 4;          // 0..28
            float4 av = *(const float4*)(A + (size_t)(bm + r) * D_MODEL + k0 + c);
            float4 wv = *(const float4*)(W + (size_t)(bn + r) * D_MODEL + k0 + c);
            uint32_t* pa = &As[r * PLD + c];
            uint32_t* pb = &Bs[r * PLD + c];
            pa[0] = f2tf32(av.x); pa[1] = f2tf32(av.y);
            pa[2] = f2tf32(av.z); pa[3] = f2tf32(av.w);
            pb[0] = f2tf32(wv.x); pb[1] = f2tf32(wv.y);
            pb[2] = f2tf32(wv.z); pb[3] = f2tf32(wv.w);
        }
        __syncthreads();

        #pragma unroll
        for (int ks = 0; ks < PBK; ks += 8) {
            uint32_t afr[4][4], bfr[4][2];
            #pragma unroll
            for (int mi = 0; mi < 4; mi++) {
                const int r0 = (wm * 64 + mi * 16 + g) * PLD;
                afr[mi][0] = As[r0 + ks + tg];
                afr[mi][1] = As[r0 + 8 * PLD + ks + tg];
                afr[mi][2] = As[r0 + ks + tg + 4];
                afr[mi][3] = As[r0 + 8 * PLD + ks + tg + 4];
            }
            #pragma unroll
            for (int ni = 0; ni < 4; ni++) {
                const int nb = (wn * 32 + ni * 8 + g) * PLD;
                bfr[ni][0] = Bs[nb + ks + tg];
                bfr[ni][1] = Bs[nb + ks + tg + 4];
            }
            #pragma unroll
            for (int mi = 0; mi < 4; mi++)
                #pragma unroll
                for (int ni = 0; ni < 4; ni++)
                    mma_tf32_16x8x8(acc[mi][ni], afr[mi], bfr[ni]);
        }
        __syncthreads();
    }

    // epilogue
    #pragma unroll
    for (int mi = 0; mi < 4; mi++) {
        #pragma unroll
        for (int ni = 0; ni < 4; ni++) {
            const int col = bn + wn * 32 + ni * 8 + tg * 2;
            const float2 bv = *(const float2*)(bias + col);
            #pragma unroll
            for (int half = 0; half < 2; half++) {
                const int m = bm + wm * 64 + mi * 16 + g + half * 8;
                float2 o;
                o.x = acc[mi][ni][half * 2 + 0] + bv.x;
                o.y = acc[mi][ni][half * 2 + 1] + bv.y;
                if (SPLIT) {
                    const int b = m >> 11, sq = m & 2047;
                    const int h = col >> 6, d = col & 63;
                    *(float2*)(out + (((size_t)(b * NHEADS + h) * SEQ) + sq) * DEPTH + d) = o;
                } else {
                    *(float2*)(out + (size_t)m * D_MODEL + col) = o;
                }
            }
        }
    }
}

// ---------------- flash attention: 64x64 tiles, depth 64 (unchanged) --------
constexpr int FB   = 64;
constexpr int FSTR = 68;

__global__ __launch_bounds__(256)
void flash_attn(const int* __restrict__ mask) {
    extern __shared__ float sm[];
    float* Qs  = sm;
    float* Ks  = Qs + FB*FSTR;
    float* Vs  = Ks + FB*FSTR;
    float* Ps  = Vs + FB*FSTR;
    float* pen = Ps + FB*FSTR;

    const int qt  = blockIdx.x;
    const int h   = blockIdx.y;
    const int b   = blockIdx.z;
    const int tid = threadIdx.x;
    const int ty = tid >> 4, tx = tid & 15;
    const int r0 = ty * 4, c0 = tx * 4;

    const float* qbase = g_q + ((size_t)(b*NHEADS + h) * SEQ + qt*FB) * DEPTH;
    const float* kbase = g_k + (size_t)(b*NHEADS + h) * SEQ * DEPTH;
    const float* vbase = g_v + (size_t)(b*NHEADS + h) * SEQ * DEPTH;

    for (int i = tid; i < FB * (DEPTH/4); i += 256) {
        const int r = i >> 4, c4 = (i & 15) * 4;
        float4 v = *(const float4*)(qbase + r*DEPTH + c4);
        Qs[r*FSTR + c4 + 0] = v.x * 0.125f;
        Qs[r*FSTR + c4 + 1] = v.y * 0.125f;
        Qs[r*FSTR + c4 + 2] = v.z * 0.125f;
        Qs[r*FSTR + c4 + 3] = v.w * 0.125f;
    }

    float m_i[4] = {-1e30f, -1e30f, -1e30f, -1e30f};
    float l_i[4] = {0.f, 0.f, 0.f, 0.f};
    float acc[4][4] = {};

    for (int kt = 0; kt < SEQ/FB; kt++) {
        __syncthreads();
        for (int i = tid; i < FB * (DEPTH/4); i += 256) {
            const int r = i >> 4, c4 = (i & 15) * 4;
            float4 kv = *(const float4*)(kbase + (size_t)(kt*FB + r)*DEPTH + c4);
            float4 vv = *(const float4*)(vbase + (size_t)(kt*FB + r)*DEPTH + c4);
            Ks[r*FSTR + c4 + 0] = kv.x; Ks[r*FSTR + c4 + 1] = kv.y;
            Ks[r*FSTR + c4 + 2] = kv.z; Ks[r*FSTR + c4 + 3] = kv.w;
            Vs[r*FSTR + c4 + 0] = vv.x; Vs[r*FSTR + c4 + 1] = vv.y;
            Vs[r*FSTR + c4 + 2] = vv.z; Vs[r*FSTR + c4 + 3] = vv.w;
        }
        if (tid < FB)
            pen[tid] = -1e9f * (float)mask[b*SEQ + kt*FB + tid];
        __syncthreads();

        float s[4][4] = {};
        #pragma unroll
        for (int kk = 0; kk < DEPTH; kk += 4) {
            float4 q4[4], k4[4];
            #pragma unroll
            for (int i = 0; i < 4; i++) q4[i] = *(const float4*)&Qs[(r0+i)*FSTR + kk];
            #pragma unroll
            for (int j = 0; j < 4; j++) k4[j] = *(const float4*)&Ks[(c0+j)*FSTR + kk];
            #pragma unroll
            for (int i = 0; i < 4; i++)
                #pragma unroll
                for (int j = 0; j < 4; j++)
                    s[i][j] += q4[i].x*k4[j].x + q4[i].y*k4[j].y
                             + q4[i].z*k4[j].z + q4[i].w*k4[j].w;
        }

        #pragma unroll
        for (int i = 0; i < 4; i++) {
            #pragma unroll
            for (int j = 0; j < 4; j++) s[i][j] += pen[c0 + j];
            float mx = fmaxf(fmaxf(s[i][0], s[i][1]), fmaxf(s[i][2], s[i][3]));
            #pragma unroll
            for (int off = 1; off < 16; off <<= 1)
                mx = fmaxf(mx, __shfl_xor_sync(0xffffffffu, mx, off));
            const float mnew = fmaxf(m_i[i], mx);
            const float corr = __expf(m_i[i] - mnew);
            float rsum = 0.f;
            #pragma unroll
            for (int j = 0; j < 4; j++) { s[i][j] = __expf(s[i][j] - mnew); rsum += s[i][j]; }
            #pragma unroll
            for (int off = 1; off < 16; off <<= 1)
                rsum += __shfl_xor_sync(0xffffffffu, rsum, off);
            l_i[i] = l_i[i] * corr + rsum;
            m_i[i] = mnew;
            #pragma unroll
            for (int j = 0; j < 4; j++) acc[i][j] *= corr;
            #pragma unroll
            for (int j = 0; j < 4; j++) Ps[(r0+i)*FSTR + c0 + j] = s[i][j];
        }
        __syncthreads();

        #pragma unroll
        for (int kk = 0; kk < FB; kk += 4) {
            float4 p4[4], v4[4];
            #pragma unroll
            for (int i = 0; i < 4; i++) p4[i] = *(const float4*)&Ps[(r0+i)*FSTR + kk];
            #pragma unroll
            for (int u = 0; u < 4; u++) v4[u] = *(const float4*)&Vs[(kk+u)*FSTR + c0];
            #pragma unroll
            for (int i = 0; i < 4; i++) {
                acc[i][0] += p4[i].x*v4[0].x + p4[i].y*v4[1].x + p4[i].z*v4[2].x + p4[i].w*v4[3].x;
                acc[i][1] += p4[i].x*v4[0].y + p4[i].y*v4[1].y + p4[i].z*v4[2].y + p4[i].w*v4[3].y;
                acc[i][2] += p4[i].x*v4[0].z + p4[i].y*v4[1].z + p4[i].z*v4[2].z + p4[i].w*v4[3].z;
                acc[i][3] += p4[i].x*v4[0].w + p4[i].y*v4[1].w + p4[i].z*v4[2].w + p4[i].w*v4[3].w;
            }
        }
    }

    #pragma unroll
    for (int i = 0; i < 4; i++) {
        const float inv = 1.0f / l_i[i];
        const int row = qt*FB + r0 + i;
        float* o = g_ctx + ((size_t)b*SEQ + row) * D_MODEL + h*DEPTH + c0;
        #pragma unroll
        for (int j = 0; j < 4; j++) o[j] = acc[i][j] * inv;
    }
}

// ---------------------------------------------------------------------------
extern "C" void kernel_launch(void* const* d_in, const int* in_sizes, int n_in,
                              void* d_out, int out_size) {
    const float* query = (const float*)d_in[0];
    const float* key   = (const float*)d_in[1];
    const float* value = (const float*)d_in[2];
    const int*   mask  = (const int*)  d_in[3];
    const float* Wq = (const float*)d_in[4];
    const float* bq = (const float*)d_in[5];
    const float* Wk = (const float*)d_in[6];
    const float* bk = (const float*)d_in[7];
    const float* Wv = (const float*)d_in[8];
    const float* bv = (const float*)d_in[9];
    const float* Wo = (const float*)d_in[10];
    const float* bo = (const float*)d_in[11];
    float* out = (float*)d_out;

    void *pq, *pk, *pv, *pctx;
    cudaGetSymbolAddress(&pq,   g_q);
    cudaGetSymbolAddress(&pk,   g_k);
    cudaGetSymbolAddress(&pv,   g_v);
    cudaGetSymbolAddress(&pctx, g_ctx);

    const dim3 gg(D_MODEL / PBN, MTOT / PBM);   // (8, 32)

    proj_mma<1><<<gg, 256>>>(query, Wq, bq, (float*)pq);
    proj_mma<1><<<gg, 256>>>(key,   Wk, bk, (float*)pk);
    proj_mma<1><<<gg, 256>>>(value, Wv, bv, (float*)pv);

    const int smem_bytes = (4 * FB * FSTR + FB) * (int)sizeof(float);
    cudaFuncSetAttribute(flash_attn, cudaFuncAttributeMaxDynamicSharedMemorySize,
                         smem_bytes);
    flash_attn<<<dim3(SEQ/FB, NHEADS, BATCH), 256, smem_bytes>>>(mask);

    proj_mma<0><<<gg, 256>>>((const float*)pctx, Wo, bo, out);
}

// round 4
// speedup vs baseline: 3.2979x; 2.4523x over previous
#include <cuda_runtime.h>
#include <cstdint>
#include <math.h>

#define D_MODEL 1024
#define NHEADS  16
#define DEPTH   64
#define BATCH   2
#define SEQ     2048
#define MTOT    (BATCH*SEQ)   // 4096

// ---------------- scratch (device globals; no allocations allowed) ----------
__device__ float g_q[BATCH*NHEADS*SEQ*DEPTH];   // 16 MB, [B,H,S,64]
__device__ float g_k[BATCH*NHEADS*SEQ*DEPTH];
__device__ float g_v[BATCH*NHEADS*SEQ*DEPTH];
__device__ float g_ctx[BATCH*SEQ*D_MODEL];      // 16 MB, [B,S,1024]

// ---------------- mma.sync tf32 helpers (base-target, lowers to HMMA) ------
__device__ __forceinline__ uint32_t f2tf32(float x) {
    uint32_t r;
    asm("cvt.rna.tf32.f32 %0, %1;" : "=r"(r) : "f"(x));
    return r;
}
__device__ __forceinline__ void mma_tf32_16x8x8(float* d, const uint32_t* a,
                                                const uint32_t* b) {
    asm volatile(
        "mma.sync.aligned.m16n8k8.row.col.f32.tf32.tf32.f32 "
        "{%0,%1,%2,%3}, {%4,%5,%6,%7}, {%8,%9}, {%0,%1,%2,%3};"
        : "+f"(d[0]), "+f"(d[1]), "+f"(d[2]), "+f"(d[3])
        : "r"(a[0]), "r"(a[1]), "r"(a[2]), "r"(a[3]), "r"(b[0]), "r"(b[1]));
}

// ============ tf32 tensor-core projection: out = A[M,K] @ W[N,K]^T + bias ===
constexpr int PBM = 128, PBN = 128, PBK = 32, PLD = PBK + 4;   // PLD=36

template<int SPLIT>
__global__ __launch_bounds__(256)
void proj_mma(const float* __restrict__ A, const float* __restrict__ W,
              const float* __restrict__ bias, float* __restrict__ out) {
    __shared__ uint32_t As[PBM * PLD];
    __shared__ uint32_t Bs[PBN * PLD];

    const int tid  = threadIdx.x;
    const int wid  = tid >> 5;
    const int lane = tid & 31;
    const int g    = lane >> 2;
    const int tg   = lane & 3;
    const int wm   = wid >> 2;
    const int wn   = wid & 3;
    const int bm   = blockIdx.y * PBM;
    const int bn   = blockIdx.x * PBN;

    float acc[4][4][4] = {};

    for (int k0 = 0; k0 < D_MODEL; k0 += PBK) {
        #pragma unroll
        for (int i = 0; i < 4; i++) {
            const int idx = tid + i * 256;
            const int r = idx >> 3;
            const int c = (idx & 7) * 4;
            float4 av = *(const float4*)(A + (size_t)(bm + r) * D_MODEL + k0 + c);
            float4 wv = *(const float4*)(W + (size_t)(bn + r) * D_MODEL + k0 + c);
            uint32_t* pa = &As[r * PLD + c];
            uint32_t* pb = &Bs[r * PLD + c];
            pa[0] = f2tf32(av.x); pa[1] = f2tf32(av.y);
            pa[2] = f2tf32(av.z); pa[3] = f2tf32(av.w);
            pb[0] = f2tf32(wv.x); pb[1] = f2tf32(wv.y);
            pb[2] = f2tf32(wv.z); pb[3] = f2tf32(wv.w);
        }
        __syncthreads();

        #pragma unroll
        for (int ks = 0; ks < PBK; ks += 8) {
            uint32_t afr[4][4], bfr[4][2];
            #pragma unroll
            for (int mi = 0; mi < 4; mi++) {
                const int r0 = (wm * 64 + mi * 16 + g) * PLD;
                afr[mi][0] = As[r0 + ks + tg];
                afr[mi][1] = As[r0 + 8 * PLD + ks + tg];
                afr[mi][2] = As[r0 + ks + tg + 4];
                afr[mi][3] = As[r0 + 8 * PLD + ks + tg + 4];
            }
            #pragma unroll
            for (int ni = 0; ni < 4; ni++) {
                const int nb = (wn * 32 + ni * 8 + g) * PLD;
                bfr[ni][0] = Bs[nb + ks + tg];
                bfr[ni][1] = Bs[nb + ks + tg + 4];
            }
            #pragma unroll
            for (int mi = 0; mi < 4; mi++)
                #pragma unroll
                for (int ni = 0; ni < 4; ni++)
                    mma_tf32_16x8x8(acc[mi][ni], afr[mi], bfr[ni]);
        }
        __syncthreads();
    }

    #pragma unroll
    for (int mi = 0; mi < 4; mi++) {
        #pragma unroll
        for (int ni = 0; ni < 4; ni++) {
            const int col = bn + wn * 32 + ni * 8 + tg * 2;
            const float2 bv = *(const float2*)(bias + col);
            #pragma unroll
            for (int half = 0; half < 2; half++) {
                const int m = bm + wm * 64 + mi * 16 + g + half * 8;
                float2 o;
                o.x = acc[mi][ni][half * 2 + 0] + bv.x;
                o.y = acc[mi][ni][half * 2 + 1] + bv.y;
                if (SPLIT) {
                    const int b = m >> 11, sq = m & 2047;
                    const int h = col >> 6, d = col & 63;
                    *(float2*)(out + (((size_t)(b * NHEADS + h) * SEQ) + sq) * DEPTH + d) = o;
                } else {
                    *(float2*)(out + (size_t)m * D_MODEL + col) = o;
                }
            }
        }
    }
}

// ================= tensor-core flash attention ===============================
// CTA: 128 threads (4 warps). Q tile 64 rows (16/warp), K tile 64 per iter.
// QK^T: split-precision (Q = hi+lo tf32, K single tf32) -> 2 MMAs/step.
// P@V: single tf32. Padded smem stride 68 -> conflict-free fragment loads.
constexpr int FQ  = 64;
constexpr int FK  = 64;
constexpr int FLD = 68;

constexpr int W_QHI = 0;
constexpr int W_QLO = W_QHI + FQ * FLD;   // 4352
constexpr int W_K   = W_QLO + FQ * FLD;   // 8704
constexpr int W_V   = W_K   + FK * FLD;   // 13056
constexpr int W_P   = W_V   + FK * FLD;   // 17408
constexpr int W_PEN = W_P   + FQ * FLD;   // 21760
constexpr int FLASH_SMEM = (W_PEN + FK) * 4;   // 87296 bytes

__global__ __launch_bounds__(128)
void flash_mma(const int* __restrict__ mask) {
    extern __shared__ uint32_t sw[];
    float* pen = (float*)(sw + W_PEN);

    const int qt = blockIdx.x, h = blockIdx.y, b = blockIdx.z;
    const int tid  = threadIdx.x;
    const int w    = tid >> 5;
    const int lane = tid & 31;
    const int g    = lane >> 2;
    const int tg   = lane & 3;

    const float* qbase = g_q + ((size_t)(b*NHEADS + h) * SEQ + qt*FQ) * DEPTH;
    const float* kbase = g_k + (size_t)(b*NHEADS + h) * SEQ * DEPTH;
    const float* vbase = g_v + (size_t)(b*NHEADS + h) * SEQ * DEPTH;

    // stage Q (scaled by 1/8), split into tf32 hi + lo
    #pragma unroll
    for (int i = 0; i < 8; i++) {
        const int idx = tid + i * 128;           // 1024 float4 slots
        const int r = idx >> 4, c4 = (idx & 15) << 2;
        float4 v = *(const float4*)(qbase + r * DEPTH + c4);
        float xs[4] = {v.x * 0.125f, v.y * 0.125f, v.z * 0.125f, v.w * 0.125f};
        uint4 hi, lo;
        hi.x = f2tf32(xs[0]); lo.x = f2tf32(xs[0] - __uint_as_float(hi.x));
        hi.y = f2tf32(xs[1]); lo.y = f2tf32(xs[1] - __uint_as_float(hi.y));
        hi.z = f2tf32(xs[2]); lo.z = f2tf32(xs[2] - __uint_as_float(hi.z));
        hi.w = f2tf32(xs[3]); lo.w = f2tf32(xs[3] - __uint_as_float(hi.w));
        *(uint4*)(sw + W_QHI + r * FLD + c4) = hi;
        *(uint4*)(sw + W_QLO + r * FLD + c4) = lo;
    }

    float m0 = -1e30f, m1 = -1e30f, l0 = 0.f, l1 = 0.f;
    float oac[8][4] = {};

    for (int kt = 0; kt < SEQ / FK; kt++) {
        __syncthreads();   // smem reuse guard (also orders initial Q stores)
        #pragma unroll
        for (int i = 0; i < 8; i++) {
            const int idx = tid + i * 128;
            const int r = idx >> 4, c4 = (idx & 15) << 2;
            float4 kv = *(const float4*)(kbase + (size_t)(kt*FK + r) * DEPTH + c4);
            float4 vv = *(const float4*)(vbase + (size_t)(kt*FK + r) * DEPTH + c4);
            uint4 kk = make_uint4(f2tf32(kv.x), f2tf32(kv.y), f2tf32(kv.z), f2tf32(kv.w));
            uint4 vt = make_uint4(f2tf32(vv.x), f2tf32(vv.y), f2tf32(vv.z), f2tf32(vv.w));
            *(uint4*)(sw + W_K + r * FLD + c4) = kk;
            *(uint4*)(sw + W_V + r * FLD + c4) = vt;
        }
        if (tid < FK)
            pen[tid] = -1e9f * (float)mask[b*SEQ + kt*FK + tid];
        __syncthreads();

        // ---- S = Q @ K^T (split-precision) ----
        float sac[8][4] = {};
        #pragma unroll
        for (int ks = 0; ks < 8; ks++) {
            uint32_t ahi[4], alo[4];
            const uint32_t* qh = sw + W_QHI + (w*16 + g) * FLD + ks*8 + tg;
            const uint32_t* ql = sw + W_QLO + (w*16 + g) * FLD + ks*8 + tg;
            ahi[0] = qh[0]; ahi[1] = qh[8*FLD]; ahi[2] = qh[4]; ahi[3] = qh[8*FLD + 4];
            alo[0] = ql[0]; alo[1] = ql[8*FLD]; alo[2] = ql[4]; alo[3] = ql[8*FLD + 4];
            #pragma unroll
            for (int nf = 0; nf < 8; nf++) {
                uint32_t bf[2];
                const uint32_t* kp = sw + W_K + (nf*8 + g) * FLD + ks*8 + tg;
                bf[0] = kp[0]; bf[1] = kp[4];
                mma_tf32_16x8x8(sac[nf], ahi, bf);
                mma_tf32_16x8x8(sac[nf], alo, bf);
            }
        }

        // ---- mask + online softmax ----
        #pragma unroll
        for (int nf = 0; nf < 8; nf++) {
            const float p0 = pen[nf*8 + 2*tg], p1 = pen[nf*8 + 2*tg + 1];
            sac[nf][0] += p0; sac[nf][1] += p1;
            sac[nf][2] += p0; sac[nf][3] += p1;
        }
        float mx0 = -1e30f, mx1 = -1e30f;
        #pragma unroll
        for (int nf = 0; nf < 8; nf++) {
            mx0 = fmaxf(mx0, fmaxf(sac[nf][0], sac[nf][1]));
            mx1 = fmaxf(mx1, fmaxf(sac[nf][2], sac[nf][3]));
        }
        mx0 = fmaxf(mx0, __shfl_xor_sync(0xffffffffu, mx0, 1));
        mx0 = fmaxf(mx0, __shfl_xor_sync(0xffffffffu, mx0, 2));
        mx1 = fmaxf(mx1, __shfl_xor_sync(0xffffffffu, mx1, 1));
        mx1 = fmaxf(mx1, __shfl_xor_sync(0xffffffffu, mx1, 2));
        const float mn0 = fmaxf(m0, mx0), mn1 = fmaxf(m1, mx1);
        const float c0 = __expf(m0 - mn0), c1 = __expf(m1 - mn1);
        float s0 = 0.f, s1 = 0.f;
        #pragma unroll
        for (int nf = 0; nf < 8; nf++) {
            const float e0 = __expf(sac[nf][0] - mn0);
            const float e1 = __expf(sac[nf][1] - mn0);
            const float e2 = __expf(sac[nf][2] - mn1);
            const float e3 = __expf(sac[nf][3] - mn1);
            s0 += e0 + e1; s1 += e2 + e3;
            uint2 r0; r0.x = f2tf32(e0); r0.y = f2tf32(e1);
            uint2 r1; r1.x = f2tf32(e2); r1.y = f2tf32(e3);
            *(uint2*)(sw + W_P + (w*16 + g    ) * FLD + nf*8 + 2*tg) = r0;
            *(uint2*)(sw + W_P + (w*16 + g + 8) * FLD + nf*8 + 2*tg) = r1;
        }
        s0 += __shfl_xor_sync(0xffffffffu, s0, 1);
        s0 += __shfl_xor_sync(0xffffffffu, s0, 2);
        s1 += __shfl_xor_sync(0xffffffffu, s1, 1);
        s1 += __shfl_xor_sync(0xffffffffu, s1, 2);
        l0 = l0 * c0 + s0; l1 = l1 * c1 + s1;
        m0 = mn0; m1 = mn1;
        #pragma unroll
        for (int nf = 0; nf < 8; nf++) {
            oac[nf][0] *= c0; oac[nf][1] *= c0;
            oac[nf][2] *= c1; oac[nf][3] *= c1;
        }
        __syncwarp();   // P stores (cross-lane) visible before fragment reads

        // ---- O += P @ V ----
        #pragma unroll
        for (int ks = 0; ks < 8; ks++) {
            uint32_t a[4];
            const uint32_t* pp = sw + W_P + (w*16 + g) * FLD + ks*8 + tg;
            a[0] = pp[0]; a[1] = pp[8*FLD]; a[2] = pp[4]; a[3] = pp[8*FLD + 4];
            #pragma unroll
            for (int nf = 0; nf < 8; nf++) {
                uint32_t bf[2];
                const uint32_t* vp = sw + W_V + (ks*8 + tg) * FLD + nf*8 + g;
                bf[0] = vp[0]; bf[1] = vp[4*FLD];
                mma_tf32_16x8x8(oac[nf], a, bf);
            }
        }
    }

    // epilogue: merged-head context [B,S,1024]
    const float il0 = 1.0f / l0, il1 = 1.0f / l1;
    const int row0 = qt*FQ + w*16 + g;
    float* ob = g_ctx + ((size_t)b*SEQ + row0) * D_MODEL + h*DEPTH;
    #pragma unroll
    for (int nf = 0; nf < 8; nf++) {
        const int c = nf*8 + 2*tg;
        float2 o0; o0.x = oac[nf][0] * il0; o0.y = oac[nf][1] * il0;
        float2 o1; o1.x = oac[nf][2] * il1; o1.y = oac[nf][3] * il1;
        *(float2*)(ob + c) = o0;
        *(float2*)(ob + (size_t)8 * D_MODEL + c) = o1;
    }
}

// ---------------------------------------------------------------------------
extern "C" void kernel_launch(void* const* d_in, const int* in_sizes, int n_in,
                              void* d_out, int out_size) {
    const float* query = (const float*)d_in[0];
    const float* key   = (const float*)d_in[1];
    const float* value = (const float*)d_in[2];
    const int*   mask  = (const int*)  d_in[3];
    const float* Wq = (const float*)d_in[4];
    const float* bq = (const float*)d_in[5];
    const float* Wk = (const float*)d_in[6];
    const float* bk = (const float*)d_in[7];
    const float* Wv = (const float*)d_in[8];
    const float* bv = (const float*)d_in[9];
    const float* Wo = (const float*)d_in[10];
    const float* bo = (const float*)d_in[11];
    float* out = (float*)d_out;

    void *pq, *pk, *pv, *pctx;
    cudaGetSymbolAddress(&pq,   g_q);
    cudaGetSymbolAddress(&pk,   g_k);
    cudaGetSymbolAddress(&pv,   g_v);
    cudaGetSymbolAddress(&pctx, g_ctx);

    const dim3 gg(D_MODEL / PBN, MTOT / PBM);   // (8, 32)

    proj_mma<1><<<gg, 256>>>(query, Wq, bq, (float*)pq);
    proj_mma<1><<<gg, 256>>>(key,   Wk, bk, (float*)pk);
    proj_mma<1><<<gg, 256>>>(value, Wv, bv, (float*)pv);

    cudaFuncSetAttribute(flash_mma, cudaFuncAttributeMaxDynamicSharedMemorySize,
                         FLASH_SMEM);
    flash_mma<<<dim3(SEQ/FQ, NHEADS, BATCH), 128, FLASH_SMEM>>>(mask);

    proj_mma<0><<<gg, 256>>>((const float*)pctx, Wo, bo, out);
}

// round 5
// speedup vs baseline: 3.6910x; 1.1192x over previous
#include <cuda_runtime.h>
#include <cstdint>
#include <math.h>

#define D_MODEL 1024
#define NHEADS  16
#define DEPTH   64
#define BATCH   2
#define SEQ     2048
#define MTOT    (BATCH*SEQ)   // 4096

// ---------------- scratch (device globals; no allocations allowed) ----------
__device__ float g_q[BATCH*NHEADS*SEQ*DEPTH];   // 16 MB, [B,H,S,64]
__device__ float g_k[BATCH*NHEADS*SEQ*DEPTH];
__device__ float g_v[BATCH*NHEADS*SEQ*DEPTH];
__device__ float g_ctx[BATCH*SEQ*D_MODEL];      // 16 MB, [B,S,1024]

// ---------------- mma.sync tf32 helpers (base-target, lowers to HMMA) ------
__device__ __forceinline__ uint32_t f2tf32(float x) {
    uint32_t r;
    asm("cvt.rna.tf32.f32 %0, %1;" : "=r"(r) : "f"(x));
    return r;
}
__device__ __forceinline__ void mma_tf32_16x8x8(float* d, const uint32_t* a,
                                                const uint32_t* b) {
    asm volatile(
        "mma.sync.aligned.m16n8k8.row.col.f32.tf32.tf32.f32 "
        "{%0,%1,%2,%3}, {%4,%5,%6,%7}, {%8,%9}, {%0,%1,%2,%3};"
        : "+f"(d[0]), "+f"(d[1]), "+f"(d[2]), "+f"(d[3])
        : "r"(a[0]), "r"(a[1]), "r"(a[2]), "r"(a[3]), "r"(b[0]), "r"(b[1]));
}

// ============ tf32 tensor-core projection: out = A[M,K] @ W[N,K]^T + bias ===
constexpr int PBM = 128, PBN = 128, PBK = 32, PLD = PBK + 4;   // PLD=36

template<int SPLIT>
__device__ __forceinline__
void proj_body(uint32_t* As, uint32_t* Bs,
               const float* __restrict__ A, const float* __restrict__ W,
               const float* __restrict__ bias, float* __restrict__ out) {
    const int tid  = threadIdx.x;
    const int wid  = tid >> 5;
    const int lane = tid & 31;
    const int g    = lane >> 2;
    const int tg   = lane & 3;
    const int wm   = wid >> 2;
    const int wn   = wid & 3;
    const int bm   = blockIdx.y * PBM;
    const int bn   = blockIdx.x * PBN;

    float acc[4][4][4] = {};

    for (int k0 = 0; k0 < D_MODEL; k0 += PBK) {
        #pragma unroll
        for (int i = 0; i < 4; i++) {
            const int idx = tid + i * 256;
            const int r = idx >> 3;
            const int c = (idx & 7) * 4;
            float4 av = *(const float4*)(A + (size_t)(bm + r) * D_MODEL + k0 + c);
            float4 wv = *(const float4*)(W + (size_t)(bn + r) * D_MODEL + k0 + c);
            uint32_t* pa = &As[r * PLD + c];
            uint32_t* pb = &Bs[r * PLD + c];
            pa[0] = f2tf32(av.x); pa[1] = f2tf32(av.y);
            pa[2] = f2tf32(av.z); pa[3] = f2tf32(av.w);
            pb[0] = f2tf32(wv.x); pb[1] = f2tf32(wv.y);
            pb[2] = f2tf32(wv.z); pb[3] = f2tf32(wv.w);
        }
        __syncthreads();

        #pragma unroll
        for (int ks = 0; ks < PBK; ks += 8) {
            uint32_t afr[4][4], bfr[4][2];
            #pragma unroll
            for (int mi = 0; mi < 4; mi++) {
                const int r0 = (wm * 64 + mi * 16 + g) * PLD;
                afr[mi][0] = As[r0 + ks + tg];
                afr[mi][1] = As[r0 + 8 * PLD + ks + tg];
                afr[mi][2] = As[r0 + ks + tg + 4];
                afr[mi][3] = As[r0 + 8 * PLD + ks + tg + 4];
            }
            #pragma unroll
            for (int ni = 0; ni < 4; ni++) {
                const int nb = (wn * 32 + ni * 8 + g) * PLD;
                bfr[ni][0] = Bs[nb + ks + tg];
                bfr[ni][1] = Bs[nb + ks + tg + 4];
            }
            #pragma unroll
            for (int mi = 0; mi < 4; mi++)
                #pragma unroll
                for (int ni = 0; ni < 4; ni++)
                    mma_tf32_16x8x8(acc[mi][ni], afr[mi], bfr[ni]);
        }
        __syncthreads();
    }

    #pragma unroll
    for (int mi = 0; mi < 4; mi++) {
        #pragma unroll
        for (int ni = 0; ni < 4; ni++) {
            const int col = bn + wn * 32 + ni * 8 + tg * 2;
            const float2 bv = *(const float2*)(bias + col);
            #pragma unroll
            for (int half = 0; half < 2; half++) {
                const int m = bm + wm * 64 + mi * 16 + g + half * 8;
                float2 o;
                o.x = acc[mi][ni][half * 2 + 0] + bv.x;
                o.y = acc[mi][ni][half * 2 + 1] + bv.y;
                if (SPLIT) {
                    const int b = m >> 11, sq = m & 2047;
                    const int h = col >> 6, d = col & 63;
                    *(float2*)(out + (((size_t)(b * NHEADS + h) * SEQ) + sq) * DEPTH + d) = o;
                } else {
                    *(float2*)(out + (size_t)m * D_MODEL + col) = o;
                }
            }
        }
    }
}

// one launch for Q, K, V projections (blockIdx.z selects)
__global__ __launch_bounds__(256)
void proj_qkv(const float* __restrict__ q, const float* __restrict__ k,
              const float* __restrict__ v,
              const float* __restrict__ Wq, const float* __restrict__ bq,
              const float* __restrict__ Wk, const float* __restrict__ bk,
              const float* __restrict__ Wv, const float* __restrict__ bv) {
    __shared__ uint32_t As[PBM * PLD];
    __shared__ uint32_t Bs[PBN * PLD];
    const float *A, *W, *bias;
    float* out;
    if (blockIdx.z == 0)      { A = q; W = Wq; bias = bq; out = g_q; }
    else if (blockIdx.z == 1) { A = k; W = Wk; bias = bk; out = g_k; }
    else                      { A = v; W = Wv; bias = bv; out = g_v; }
    proj_body<1>(As, Bs, A, W, bias, out);
}

__global__ __launch_bounds__(256)
void proj_o(const float* __restrict__ W, const float* __restrict__ bias,
            float* __restrict__ out) {
    __shared__ uint32_t As[PBM * PLD];
    __shared__ uint32_t Bs[PBN * PLD];
    proj_body<0>(As, Bs, g_ctx, W, bias, out);
}

// ================= tensor-core flash attention v3 ============================
// CTA: 256 threads (8 warps). Q tile 128 rows (16/warp), K tile 64 per iter.
// K/V prefetched into registers one iteration ahead (hides L2 latency).
// QK^T split-precision (Q hi+lo tf32); P@V single tf32.
constexpr int FQ  = 128;
constexpr int FK  = 64;
constexpr int FLD = 68;

constexpr int W_QHI = 0;
constexpr int W_QLO = W_QHI + FQ * FLD;   // 8704
constexpr int W_K   = W_QLO + FQ * FLD;   // 17408
constexpr int W_V   = W_K   + FK * FLD;   // 21760
constexpr int W_P   = W_V   + FK * FLD;   // 26112
constexpr int W_PEN = W_P   + FQ * FLD;   // 34816
constexpr int FLASH_SMEM = (W_PEN + FK) * 4;   // 139520 bytes

__global__ __launch_bounds__(256)
void flash_mma(const int* __restrict__ mask) {
    extern __shared__ uint32_t sw[];
    float* pen = (float*)(sw + W_PEN);

    const int qt = blockIdx.x, h = blockIdx.y, b = blockIdx.z;
    const int tid  = threadIdx.x;
    const int w    = tid >> 5;
    const int lane = tid & 31;
    const int g    = lane >> 2;
    const int tg   = lane & 3;

    const float* qbase = g_q + ((size_t)(b*NHEADS + h) * SEQ + qt*FQ) * DEPTH;
    const float* kbase = g_k + (size_t)(b*NHEADS + h) * SEQ * DEPTH;
    const float* vbase = g_v + (size_t)(b*NHEADS + h) * SEQ * DEPTH;

    // stage Q (scaled by 1/8), split into tf32 hi + lo  (2048 float4 slots)
    #pragma unroll
    for (int i = 0; i < 8; i++) {
        const int idx = tid + i * 256;
        const int r = idx >> 4, c4 = (idx & 15) << 2;
        float4 v = *(const float4*)(qbase + r * DEPTH + c4);
        float xs[4] = {v.x * 0.125f, v.y * 0.125f, v.z * 0.125f, v.w * 0.125f};
        uint4 hi, lo;
        hi.x = f2tf32(xs[0]); lo.x = f2tf32(xs[0] - __uint_as_float(hi.x));
        hi.y = f2tf32(xs[1]); lo.y = f2tf32(xs[1] - __uint_as_float(hi.y));
        hi.z = f2tf32(xs[2]); lo.z = f2tf32(xs[2] - __uint_as_float(hi.z));
        hi.w = f2tf32(xs[3]); lo.w = f2tf32(xs[3] - __uint_as_float(hi.w));
        *(uint4*)(sw + W_QHI + r * FLD + c4) = hi;
        *(uint4*)(sw + W_QLO + r * FLD + c4) = lo;
    }

    // prefetch K/V tile 0 into registers (4 float4 each) + mask word
    float4 kreg[4], vreg[4];
    #pragma unroll
    for (int j = 0; j < 4; j++) {
        const int slot = tid + j * 256;
        const int r = slot >> 4, c4 = (slot & 15) << 2;
        kreg[j] = *(const float4*)(kbase + (size_t)r * DEPTH + c4);
        vreg[j] = *(const float4*)(vbase + (size_t)r * DEPTH + c4);
    }
    int pmask = (tid < FK) ? mask[b*SEQ + tid] : 0;

    float m0 = -1e30f, m1 = -1e30f, l0 = 0.f, l1 = 0.f;
    float oac[8][4] = {};

    for (int kt = 0; kt < SEQ / FK; kt++) {
        __syncthreads();   // prev iter's MMAs done with K/V/P smem; Q stores done
        #pragma unroll
        for (int j = 0; j < 4; j++) {
            const int slot = tid + j * 256;
            const int r = slot >> 4, c4 = (slot & 15) << 2;
            uint4 kk = make_uint4(f2tf32(kreg[j].x), f2tf32(kreg[j].y),
                                  f2tf32(kreg[j].z), f2tf32(kreg[j].w));
            uint4 vt = make_uint4(f2tf32(vreg[j].x), f2tf32(vreg[j].y),
                                  f2tf32(vreg[j].z), f2tf32(vreg[j].w));
            *(uint4*)(sw + W_K + r * FLD + c4) = kk;
            *(uint4*)(sw + W_V + r * FLD + c4) = vt;
        }
        if (tid < FK)
            pen[tid] = -1e9f * (float)pmask;
        __syncthreads();

        // prefetch next tile (consumed next iteration; overlaps with MMAs)
        if (kt + 1 < SEQ / FK) {
            const float* kb2 = kbase + (size_t)(kt + 1) * FK * DEPTH;
            const float* vb2 = vbase + (size_t)(kt + 1) * FK * DEPTH;
            #pragma unroll
            for (int j = 0; j < 4; j++) {
                const int slot = tid + j * 256;
                const int r = slot >> 4, c4 = (slot & 15) << 2;
                kreg[j] = *(const float4*)(kb2 + (size_t)r * DEPTH + c4);
                vreg[j] = *(const float4*)(vb2 + (size_t)r * DEPTH + c4);
            }
            if (tid < FK) pmask = mask[b*SEQ + (kt + 1)*FK + tid];
        }

        // ---- S = Q @ K^T (split-precision) ----
        float sac[8][4] = {};
        #pragma unroll
        for (int ks = 0; ks < 8; ks++) {
            uint32_t ahi[4], alo[4];
            const uint32_t* qh = sw + W_QHI + (w*16 + g) * FLD + ks*8 + tg;
            const uint32_t* ql = sw + W_QLO + (w*16 + g) * FLD + ks*8 + tg;
            ahi[0] = qh[0]; ahi[1] = qh[8*FLD]; ahi[2] = qh[4]; ahi[3] = qh[8*FLD + 4];
            alo[0] = ql[0]; alo[1] = ql[8*FLD]; alo[2] = ql[4]; alo[3] = ql[8*FLD + 4];
            #pragma unroll
            for (int nf = 0; nf < 8; nf++) {
                uint32_t bf[2];
                const uint32_t* kp = sw + W_K + (nf*8 + g) * FLD + ks*8 + tg;
                bf[0] = kp[0]; bf[1] = kp[4];
                mma_tf32_16x8x8(sac[nf], ahi, bf);
                mma_tf32_16x8x8(sac[nf], alo, bf);
            }
        }

        // ---- mask + online softmax ----
        #pragma unroll
        for (int nf = 0; nf < 8; nf++) {
            const float p0 = pen[nf*8 + 2*tg], p1 = pen[nf*8 + 2*tg + 1];
            sac[nf][0] += p0; sac[nf][1] += p1;
            sac[nf][2] += p0; sac[nf][3] += p1;
        }
        float mx0 = -1e30f, mx1 = -1e30f;
        #pragma unroll
        for (int nf = 0; nf < 8; nf++) {
            mx0 = fmaxf(mx0, fmaxf(sac[nf][0], sac[nf][1]));
            mx1 = fmaxf(mx1, fmaxf(sac[nf][2], sac[nf][3]));
        }
        mx0 = fmaxf(mx0, __shfl_xor_sync(0xffffffffu, mx0, 1));
        mx0 = fmaxf(mx0, __shfl_xor_sync(0xffffffffu, mx0, 2));
        mx1 = fmaxf(mx1, __shfl_xor_sync(0xffffffffu, mx1, 1));
        mx1 = fmaxf(mx1, __shfl_xor_sync(0xffffffffu, mx1, 2));
        const float mn0 = fmaxf(m0, mx0), mn1 = fmaxf(m1, mx1);
        const float c0 = __expf(m0 - mn0), c1 = __expf(m1 - mn1);
        float s0 = 0.f, s1 = 0.f;
        #pragma unroll
        for (int nf = 0; nf < 8; nf++) {
            const float e0 = __expf(sac[nf][0] - mn0);
            const float e1 = __expf(sac[nf][1] - mn0);
            const float e2 = __expf(sac[nf][2] - mn1);
            const float e3 = __expf(sac[nf][3] - mn1);
            s0 += e0 + e1; s1 += e2 + e3;
            uint2 r0; r0.x = f2tf32(e0); r0.y = f2tf32(e1);
            uint2 r1; r1.x = f2tf32(e2); r1.y = f2tf32(e3);
            *(uint2*)(sw + W_P + (w*16 + g    ) * FLD + nf*8 + 2*tg) = r0;
            *(uint2*)(sw + W_P + (w*16 + g + 8) * FLD + nf*8 + 2*tg) = r1;
        }
        s0 += __shfl_xor_sync(0xffffffffu, s0, 1);
        s0 += __shfl_xor_sync(0xffffffffu, s0, 2);
        s1 += __shfl_xor_sync(0xffffffffu, s1, 1);
        s1 += __shfl_xor_sync(0xffffffffu, s1, 2);
        l0 = l0 * c0 + s0; l1 = l1 * c1 + s1;
        m0 = mn0; m1 = mn1;
        #pragma unroll
        for (int nf = 0; nf < 8; nf++) {
            oac[nf][0] *= c0; oac[nf][1] *= c0;
            oac[nf][2] *= c1; oac[nf][3] *= c1;
        }
        __syncwarp();   // P stores (cross-lane within warp) visible

        // ---- O += P @ V ----
        #pragma unroll
        for (int ks = 0; ks < 8; ks++) {
            uint32_t a[4];
            const uint32_t* pp = sw + W_P + (w*16 + g) * FLD + ks*8 + tg;
            a[0] = pp[0]; a[1] = pp[8*FLD]; a[2] = pp[4]; a[3] = pp[8*FLD + 4];
            #pragma unroll
            for (int nf = 0; nf < 8; nf++) {
                uint32_t bf[2];
                const uint32_t* vp = sw + W_V + (ks*8 + tg) * FLD + nf*8 + g;
                bf[0] = vp[0]; bf[1] = vp[4*FLD];
                mma_tf32_16x8x8(oac[nf], a, bf);
            }
        }
    }

    // epilogue: merged-head context [B,S,1024]
    const float il0 = 1.0f / l0, il1 = 1.0f / l1;
    const int row0 = qt*FQ + w*16 + g;
    float* ob = g_ctx + ((size_t)b*SEQ + row0) * D_MODEL + h*DEPTH;
    #pragma unroll
    for (int nf = 0; nf < 8; nf++) {
        const int c = nf*8 + 2*tg;
        float2 o0; o0.x = oac[nf][0] * il0; o0.y = oac[nf][1] * il0;
        float2 o1; o1.x = oac[nf][2] * il1; o1.y = oac[nf][3] * il1;
        *(float2*)(ob + c) = o0;
        *(float2*)(ob + (size_t)8 * D_MODEL + c) = o1;
    }
}

// ---------------------------------------------------------------------------
extern "C" void kernel_launch(void* const* d_in, const int* in_sizes, int n_in,
                              void* d_out, int out_size) {
    const float* query = (const float*)d_in[0];
    const float* key   = (const float*)d_in[1];
    const float* value = (const float*)d_in[2];
    const int*   mask  = (const int*)  d_in[3];
    const float* Wq = (const float*)d_in[4];
    const float* bq = (const float*)d_in[5];
    const float* Wk = (const float*)d_in[6];
    const float* bk = (const float*)d_in[7];
    const float* Wv = (const float*)d_in[8];
    const float* bv = (const float*)d_in[9];
    const float* Wo = (const float*)d_in[10];
    const float* bo = (const float*)d_in[11];
    float* out = (float*)d_out;

    const dim3 gq(D_MODEL / PBN, MTOT / PBM, 3);   // (8, 32, 3)
    proj_qkv<<<gq, 256>>>(query, key, value, Wq, bq, Wk, bk, Wv, bv);

    cudaFuncSetAttribute(flash_mma, cudaFuncAttributeMaxDynamicSharedMemorySize,
                         FLASH_SMEM);
    flash_mma<<<dim3(SEQ/FQ, NHEADS, BATCH), 256, FLASH_SMEM>>>(mask);

    proj_o<<<dim3(D_MODEL / PBN, MTOT / PBM), 256>>>(Wo, bo, out);
}